// round 12
// baseline (speedup 1.0000x reference)
#include <cuda_runtime.h>
#include <cstdint>

#define BB_ 4
#define LL_ 512
#define HH_ 768
#define HS_ 64
#define OUT_ 16
#define NTOK (BB_*LL_)          // 2048
#define NPAIR ((LL_*(LL_+1))/2) // 131328
#define NSPLIT 8
#define KSLICE (HH_/NSPLIT)     // 96
#define BK_ 16
#define TILES (KSLICE/BK_)      // 6
#define BM_ 64
#define TI_ 8
#define TJ_ 64

typedef unsigned long long ull;

// f32x2 packed-fp32 helpers (FFMA2 path — PTX-only per SASS_QUICKREF)
__device__ __forceinline__ void fma2(ull& d, ull a, ull b) {
    asm("fma.rn.f32x2 %0, %1, %2, %0;" : "+l"(d) : "l"(a), "l"(b));
}
__device__ __forceinline__ ull dup2(float x) {
    ull r; asm("mov.b64 %0, {%1, %1};" : "=l"(r) : "f"(x)); return r;
}
__device__ __forceinline__ float2 un2(ull v) {
    float2 f; asm("mov.b64 {%0, %1}, %2;" : "=f"(f.x), "=f"(f.y) : "l"(v)); return f;
}

// Scratch (static device globals; no allocations allowed)
__device__ float g_part[NSPLIT][NTOK * 128];  // split-K partials
__device__ float g_q[NTOK * HS_];
__device__ float g_k[NTOK * HS_];
__device__ float g_A[NTOK * OUT_];
__device__ float g_C[NTOK * OUT_];

union F4U { float4 f; ull u[2]; };

// ---------------------------------------------------------------------------
// Kernel 1: q|k projection, split-K=8, FFMA2, TM=8 x TN=4 micro-tile.
// (Round-5 version verbatim — measured 14.3us; faster than every variant
// tried since, including mma.sync.)
// ---------------------------------------------------------------------------
__global__ __launch_bounds__(256, 2) void proj_kernel(
    const float* __restrict__ x,
    const float* __restrict__ Wq, const float* __restrict__ Wk)
{
    __shared__ __align__(16) float Xs[BM_][BK_];    // [m][kk]  4 KB
    __shared__ __align__(16) float Ws[BK_][128];    // [kk][n]  8 KB

    const int tid   = threadIdx.x;
    const int m0    = blockIdx.x * BM_;
    const int kbase = blockIdx.y * KSLICE;
    const int tx    = tid & 31;   // n = 4*tx
    const int ty    = tid >> 5;   // rows ty*8 .. ty*8+7

    const int xm = tid >> 2;
    const int xk = (tid & 3) * 4;
    const int wrow0 = tid >> 5;
    const int wcol  = (tid & 31) * 4;
    const float* wsrc = (wcol < 64) ? (Wq + wcol) : (Wk + (wcol - 64));

    float4 xr, wr0, wr1;

    xr  = *(const float4*)(x + (size_t)(m0 + xm) * HH_ + kbase + xk);
    wr0 = *(const float4*)(wsrc + (size_t)(kbase + wrow0) * HS_);
    wr1 = *(const float4*)(wsrc + (size_t)(kbase + wrow0 + 8) * HS_);
    *(float4*)(&Xs[xm][xk]) = xr;
    *(float4*)(&Ws[wrow0][wcol])     = wr0;
    *(float4*)(&Ws[wrow0 + 8][wcol]) = wr1;
    __syncthreads();

    ull acc[8][2];
    #pragma unroll
    for (int r = 0; r < 8; r++) { acc[r][0] = 0ull; acc[r][1] = 0ull; }

    for (int t = 0; t < TILES; t++) {
        if (t + 1 < TILES) {
            const int k0n = kbase + (t + 1) * BK_;
            xr  = *(const float4*)(x + (size_t)(m0 + xm) * HH_ + k0n + xk);
            wr0 = *(const float4*)(wsrc + (size_t)(k0n + wrow0) * HS_);
            wr1 = *(const float4*)(wsrc + (size_t)(k0n + wrow0 + 8) * HS_);
        }

        #pragma unroll
        for (int g = 0; g < BK_ / 4; g++) {
            float4 xf[8];
            #pragma unroll
            for (int r = 0; r < 8; r++)
                xf[r] = *(const float4*)(&Xs[ty * 8 + r][g * 4]);
            #pragma unroll
            for (int dk = 0; dk < 4; dk++) {
                float4 wv = *(const float4*)(&Ws[g * 4 + dk][tx * 4]);
                ull w0, w1;
                asm("mov.b64 %0, {%1, %2};" : "=l"(w0) : "f"(wv.x), "f"(wv.y));
                asm("mov.b64 %0, {%1, %2};" : "=l"(w1) : "f"(wv.z), "f"(wv.w));
                #pragma unroll
                for (int r = 0; r < 8; r++) {
                    const float* xp = (const float*)&xf[r];
                    ull xd = dup2(xp[dk]);
                    fma2(acc[r][0], xd, w0);
                    fma2(acc[r][1], xd, w1);
                }
            }
        }
        __syncthreads();
        if (t + 1 < TILES) {
            *(float4*)(&Xs[xm][xk]) = xr;
            *(float4*)(&Ws[wrow0][wcol])     = wr0;
            *(float4*)(&Ws[wrow0 + 8][wcol]) = wr1;
            __syncthreads();
        }
    }

    float* dst = g_part[blockIdx.y];
    #pragma unroll
    for (int r = 0; r < 8; r++) {
        float2 lo = un2(acc[r][0]), hi = un2(acc[r][1]);
        float4 v = make_float4(lo.x, lo.y, hi.x, hi.y);
        *(float4*)(dst + (size_t)(m0 + ty * 8 + r) * 128 + tx * 4) = v;
    }
}

// ---------------------------------------------------------------------------
// Kernel 2: combine 8 split-K partials + bias -> g_q/g_k, then fused A/C.
// ---------------------------------------------------------------------------
__global__ __launch_bounds__(256) void combine_kernel(
    const float* __restrict__ bq, const float* __restrict__ bk,
    const float* __restrict__ Wb, const float* __restrict__ bb)
{
    __shared__ __align__(16) float S[16][128];
    __shared__ __align__(16) float WBs[256 * 16];

    const int tid = threadIdx.x;
    const int m0  = blockIdx.x * 16;

    {
        const float4* src = (const float4*)Wb;
        float4* dst = (float4*)WBs;
        #pragma unroll
        for (int t = 0; t < 4; t++) dst[tid + 256 * t] = src[tid + 256 * t];
    }

    const size_t base4 = (size_t)m0 * 32;
    #pragma unroll
    for (int e = 0; e < 2; e++) {
        const int idx = tid + 256 * e;
        const int m   = idx >> 5;
        const int n   = (idx & 31) * 4;
        float4 v = ((const float4*)g_part[0])[base4 + idx];
        #pragma unroll
        for (int s = 1; s < NSPLIT; s++) {
            float4 p = ((const float4*)g_part[s])[base4 + idx];
            v.x += p.x; v.y += p.y; v.z += p.z; v.w += p.w;
        }
        float4 bias = (n < 64) ? *(const float4*)(bq + n)
                               : *(const float4*)(bk + (n - 64));
        v.x += bias.x; v.y += bias.y; v.z += bias.z; v.w += bias.w;
        if (n < 64) *(float4*)(g_q + (size_t)(m0 + m) * HS_ + n)        = v;
        else        *(float4*)(g_k + (size_t)(m0 + m) * HS_ + (n - 64)) = v;
        *(float4*)(&S[m][n]) = v;
    }
    __syncthreads();

    {
        const int am = tid >> 4;
        const int ao = tid & 15;
        const float* Sr = &S[am][0];
        float a = 0.f;
        float c = bb[ao];
        #pragma unroll
        for (int h = 0; h < HS_; h++) {
            float qv = Sr[h];
            float kv = Sr[64 + h];
            a += qv * WBs[h * 16 + ao];
            c += qv * WBs[(128 + h) * 16 + ao];
            c += kv * (WBs[(64 + h) * 16 + ao] + WBs[(192 + h) * 16 + ao]);
        }
        g_A[(m0 + am) * OUT_ + ao] = a;
        g_C[(m0 + am) * OUT_ + ao] = c;
    }
}

// ---------------------------------------------------------------------------
// Kernel 3: tiled pair kernel, TJ=64 for occupancy (~25 KB smem -> 8
// blocks/SM).  288 tiles/batch x 4 batches = 1152 blocks.
// ksT[c][j^c] XOR layout: staging STS and compute LDS both conflict-free
// (8-lane phase groups see bank permutations).  FFMA2 accumulation.
// Store phase: warp = i-row, lanes write consecutive float4 (coalesced).
// ---------------------------------------------------------------------------
__global__ __launch_bounds__(256) void pair_kernel(float* __restrict__ out)
{
    __shared__ __align__(16) float4 ksT[16][TJ_];   // 16 KB [c][j^c]
    __shared__ __align__(16) float4 C4s[TJ_ * 4];   // 4 KB
    __shared__ __align__(16) float4 qs4[TI_ * 16];  // 2 KB
    __shared__ __align__(16) float4 A4s[TI_ * 4];   // 512 B
    __shared__ float Sd[TI_][TJ_];                  // 2 KB

    const int b   = blockIdx.y;
    const int tid = threadIdx.x;

    // Decode tile id -> (i0, j0).  Group g = i0>>6 has 8 i-tiles x (8-g)
    // j-tiles.  Total per batch: 8 * 36 = 288.
    int id = blockIdx.x;
    int g = 0;
    while (id >= 8 * (8 - g)) { id -= 8 * (8 - g); g++; }
    const int per = 8 - g;
    const int i0  = (g * 8 + id / per) * TI_;
    const int j0  = (g + id % per) * TJ_;

    // ---- Stage tiles ----
    const float4* kg = (const float4*)(g_k + (size_t)(b * LL_ + j0) * HS_);
    #pragma unroll
    for (int e = 0; e < 4; e++) {
        const int idx = tid + 256 * e;
        const int j = idx >> 4, c = idx & 15;
        ksT[c][j ^ c] = kg[idx];
    }
    C4s[tid] = ((const float4*)(g_C + (size_t)(b * LL_ + j0) * OUT_))[tid];
    if (tid < 128) qs4[tid] = ((const float4*)(g_q + (size_t)(b * LL_ + i0) * HS_))[tid];
    if (tid < 32)  A4s[tid] = ((const float4*)(g_A + (size_t)(b * LL_ + i0) * OUT_))[tid];
    __syncthreads();

    // ---- Compute S[8][64]: thread -> rows {2ii2, 2ii2+1}, col jj ----
    {
        const int jj  = tid & 63;
        const int ii2 = tid >> 6;

        ull a0[2] = {0, 0}, a1[2] = {0, 0};
        #pragma unroll
        for (int c = 0; c < 16; c++) {
            F4U ka, qa, qb;
            ka.f = ksT[c][jj ^ c];
            qa.f = qs4[(2 * ii2 + 0) * 16 + c];
            qb.f = qs4[(2 * ii2 + 1) * 16 + c];
            fma2(a0[0], qa.u[0], ka.u[0]); fma2(a0[1], qa.u[1], ka.u[1]);
            fma2(a1[0], qb.u[0], ka.u[0]); fma2(a1[1], qb.u[1], ka.u[1]);
        }
        float2 r0, r1;
        r0 = un2(a0[0]); r1 = un2(a0[1]);
        Sd[2 * ii2 + 0][jj] = (r0.x + r0.y) + (r1.x + r1.y);
        r0 = un2(a1[0]); r1 = un2(a1[1]);
        Sd[2 * ii2 + 1][jj] = (r0.x + r0.y) + (r1.x + r1.y);
    }
    __syncthreads();

    // ---- Store phase: warp -> row ii; lanes write consecutive float4 ----
    {
        const int ii   = tid >> 5;
        const int lane = tid & 31;
        const int i    = i0 + ii;
        const int poff = i * LL_ - (i * (i - 1)) / 2;
        const float4 av = A4s[ii * 4 + (lane & 3)];
        float4* ob = (float4*)out + ((size_t)b * NPAIR + poff + (j0 - i)) * 4;

        #pragma unroll
        for (int it = 0; it < 8; it++) {
            const int idx  = lane + 32 * it;
            const int pair = idx >> 2;
            if (j0 + pair >= i) {
                const float dot = Sd[ii][pair];
                const float4 cv = C4s[idx];
                float4 r;
                r.x = dot + av.x + cv.x;
                r.y = dot + av.y + cv.y;
                r.z = dot + av.z + cv.z;
                r.w = dot + av.w + cv.w;
                ob[idx] = r;
            }
        }
    }
}

// ---------------------------------------------------------------------------
extern "C" void kernel_launch(void* const* d_in, const int* in_sizes, int n_in,
                              void* d_out, int out_size)
{
    const float* x  = (const float*)d_in[0];
    const float* Wq = (const float*)d_in[1];
    const float* bq = (const float*)d_in[2];
    const float* Wk = (const float*)d_in[3];
    const float* bk = (const float*)d_in[4];
    const float* Wb = (const float*)d_in[5];
    const float* bb = (const float*)d_in[6];
    float* out = (float*)d_out;

    proj_kernel<<<dim3(NTOK / BM_, NSPLIT), 256>>>(x, Wq, Wk);
    combine_kernel<<<NTOK / 16, 256>>>(bq, bk, Wb, bb);
    pair_kernel<<<dim3(288, BB_), 256>>>(out);
}

// round 13
// speedup vs baseline: 1.4288x; 1.4288x over previous
#include <cuda_runtime.h>
#include <cstdint>

#define BB_ 4
#define LL_ 512
#define HH_ 768
#define HS_ 64
#define OUT_ 16
#define NTOK (BB_*LL_)          // 2048
#define NPAIR ((LL_*(LL_+1))/2) // 131328
#define NSPLIT 12
#define KSLICE (HH_/NSPLIT)     // 64
#define BK_ 16
#define TILES (KSLICE/BK_)      // 4
#define BM_ 64
#define TI_ 8
#define TJ_ 128

typedef unsigned long long ull;

// f32x2 packed-fp32 helpers (FFMA2 path — PTX-only per SASS_QUICKREF)
__device__ __forceinline__ void fma2(ull& d, ull a, ull b) {
    asm("fma.rn.f32x2 %0, %1, %2, %0;" : "+l"(d) : "l"(a), "l"(b));
}
__device__ __forceinline__ ull dup2(float x) {
    ull r; asm("mov.b64 %0, {%1, %1};" : "=l"(r) : "f"(x)); return r;
}
__device__ __forceinline__ float2 un2(ull v) {
    float2 f; asm("mov.b64 {%0, %1}, %2;" : "=f"(f.x), "=f"(f.y) : "l"(v)); return f;
}

// Scratch (static device globals; no allocations allowed)
__device__ float g_part[NSPLIT][NTOK * 128];  // split-K partials
__device__ float g_q[NTOK * HS_];
__device__ float g_k[NTOK * HS_];
__device__ float g_A[NTOK * OUT_];
__device__ float g_C[NTOK * OUT_];

union F4U { float4 f; ull u[2]; };

// ---------------------------------------------------------------------------
// Kernel 1: q|k projection, split-K=12, FFMA2, TM=8 x TN=4 micro-tile.
// Grid (32, 12) = 384 blocks (2.6/SM) for latency hiding.
// ---------------------------------------------------------------------------
__global__ __launch_bounds__(256, 2) void proj_kernel(
    const float* __restrict__ x,
    const float* __restrict__ Wq, const float* __restrict__ Wk)
{
    __shared__ __align__(16) float Xs[BM_][BK_];    // [m][kk]  4 KB
    __shared__ __align__(16) float Ws[BK_][128];    // [kk][n]  8 KB

    const int tid   = threadIdx.x;
    const int m0    = blockIdx.x * BM_;
    const int kbase = blockIdx.y * KSLICE;
    const int tx    = tid & 31;   // n = 4*tx
    const int ty    = tid >> 5;   // rows ty*8 .. ty*8+7

    const int xm = tid >> 2;
    const int xk = (tid & 3) * 4;
    const int wrow0 = tid >> 5;
    const int wcol  = (tid & 31) * 4;
    const float* wsrc = (wcol < 64) ? (Wq + wcol) : (Wk + (wcol - 64));

    float4 xr, wr0, wr1;

    xr  = *(const float4*)(x + (size_t)(m0 + xm) * HH_ + kbase + xk);
    wr0 = *(const float4*)(wsrc + (size_t)(kbase + wrow0) * HS_);
    wr1 = *(const float4*)(wsrc + (size_t)(kbase + wrow0 + 8) * HS_);
    *(float4*)(&Xs[xm][xk]) = xr;
    *(float4*)(&Ws[wrow0][wcol])     = wr0;
    *(float4*)(&Ws[wrow0 + 8][wcol]) = wr1;
    __syncthreads();

    ull acc[8][2];
    #pragma unroll
    for (int r = 0; r < 8; r++) { acc[r][0] = 0ull; acc[r][1] = 0ull; }

    for (int t = 0; t < TILES; t++) {
        if (t + 1 < TILES) {
            const int k0n = kbase + (t + 1) * BK_;
            xr  = *(const float4*)(x + (size_t)(m0 + xm) * HH_ + k0n + xk);
            wr0 = *(const float4*)(wsrc + (size_t)(k0n + wrow0) * HS_);
            wr1 = *(const float4*)(wsrc + (size_t)(k0n + wrow0 + 8) * HS_);
        }

        #pragma unroll
        for (int g = 0; g < BK_ / 4; g++) {
            float4 xf[8];
            #pragma unroll
            for (int r = 0; r < 8; r++)
                xf[r] = *(const float4*)(&Xs[ty * 8 + r][g * 4]);
            #pragma unroll
            for (int dk = 0; dk < 4; dk++) {
                float4 wv = *(const float4*)(&Ws[g * 4 + dk][tx * 4]);
                ull w0, w1;
                asm("mov.b64 %0, {%1, %2};" : "=l"(w0) : "f"(wv.x), "f"(wv.y));
                asm("mov.b64 %0, {%1, %2};" : "=l"(w1) : "f"(wv.z), "f"(wv.w));
                #pragma unroll
                for (int r = 0; r < 8; r++) {
                    const float* xp = (const float*)&xf[r];
                    ull xd = dup2(xp[dk]);
                    fma2(acc[r][0], xd, w0);
                    fma2(acc[r][1], xd, w1);
                }
            }
        }
        __syncthreads();
        if (t + 1 < TILES) {
            *(float4*)(&Xs[xm][xk]) = xr;
            *(float4*)(&Ws[wrow0][wcol])     = wr0;
            *(float4*)(&Ws[wrow0 + 8][wcol]) = wr1;
            __syncthreads();
        }
    }

    float* dst = g_part[blockIdx.y];
    #pragma unroll
    for (int r = 0; r < 8; r++) {
        float2 lo = un2(acc[r][0]), hi = un2(acc[r][1]);
        float4 v = make_float4(lo.x, lo.y, hi.x, hi.y);
        *(float4*)(dst + (size_t)(m0 + ty * 8 + r) * 128 + tx * 4) = v;
    }
}

// ---------------------------------------------------------------------------
// Kernel 2: combine 12 split-K partials + bias -> g_q/g_k, then fused A/C.
// ---------------------------------------------------------------------------
__global__ __launch_bounds__(256) void combine_kernel(
    const float* __restrict__ bq, const float* __restrict__ bk,
    const float* __restrict__ Wb, const float* __restrict__ bb)
{
    __shared__ __align__(16) float S[16][128];
    __shared__ __align__(16) float WBs[256 * 16];

    const int tid = threadIdx.x;
    const int m0  = blockIdx.x * 16;

    {
        const float4* src = (const float4*)Wb;
        float4* dst = (float4*)WBs;
        #pragma unroll
        for (int t = 0; t < 4; t++) dst[tid + 256 * t] = src[tid + 256 * t];
    }

    const size_t base4 = (size_t)m0 * 32;
    #pragma unroll
    for (int e = 0; e < 2; e++) {
        const int idx = tid + 256 * e;
        const int m   = idx >> 5;
        const int n   = (idx & 31) * 4;
        float4 v = ((const float4*)g_part[0])[base4 + idx];
        #pragma unroll
        for (int s = 1; s < NSPLIT; s++) {
            float4 p = ((const float4*)g_part[s])[base4 + idx];
            v.x += p.x; v.y += p.y; v.z += p.z; v.w += p.w;
        }
        float4 bias = (n < 64) ? *(const float4*)(bq + n)
                               : *(const float4*)(bk + (n - 64));
        v.x += bias.x; v.y += bias.y; v.z += bias.z; v.w += bias.w;
        if (n < 64) *(float4*)(g_q + (size_t)(m0 + m) * HS_ + n)        = v;
        else        *(float4*)(g_k + (size_t)(m0 + m) * HS_ + (n - 64)) = v;
        *(float4*)(&S[m][n]) = v;
    }
    __syncthreads();

    {
        const int am = tid >> 4;
        const int ao = tid & 15;
        const float* Sr = &S[am][0];
        float a = 0.f;
        float c = bb[ao];
        #pragma unroll
        for (int h = 0; h < HS_; h++) {
            float qv = Sr[h];
            float kv = Sr[64 + h];
            a += qv * WBs[h * 16 + ao];
            c += qv * WBs[(128 + h) * 16 + ao];
            c += kv * (WBs[(64 + h) * 16 + ao] + WBs[(192 + h) * 16 + ao]);
        }
        g_A[(m0 + am) * OUT_ + ao] = a;
        g_C[(m0 + am) * OUT_ + ao] = c;
    }
}

// ---------------------------------------------------------------------------
// Kernel 3: tiled pair kernel — round-10 measured-best version (TJ=128,
// XOR-swizzled k layout, FFMA2 accumulation, coalesced 512B stores).
// ---------------------------------------------------------------------------
__global__ __launch_bounds__(256) void pair_kernel(float* __restrict__ out)
{
    __shared__ __align__(16) float4 ksT[16][TJ_];   // 32 KB [c][j^c]
    __shared__ __align__(16) float4 C4s[TJ_ * 4];   // 8 KB
    __shared__ __align__(16) float4 qs4[TI_ * 16];  // 2 KB
    __shared__ __align__(16) float4 A4s[TI_ * 4];   // 512 B
    __shared__ float Sd[TI_][TJ_];                  // 4 KB

    const int b   = blockIdx.y;
    const int tid = threadIdx.x;

    int id = blockIdx.x;
    int g, local;
    if      (id < 64)  { g = 0; local = id; }
    else if (id < 112) { g = 1; local = id - 64; }
    else if (id < 144) { g = 2; local = id - 112; }
    else               { g = 3; local = id - 144; }
    const int per = 4 - g;
    const int i0b = 16 * g + local / per;
    const int jt  = local % per;
    const int i0  = i0b * TI_;
    const int j0  = (g + jt) * TJ_;

    // ---- Stage tiles ----
    const float4* kg = (const float4*)(g_k + (size_t)(b * LL_ + j0) * HS_);
    #pragma unroll
    for (int e = 0; e < 8; e++) {
        const int idx = tid + 256 * e;
        const int j = idx >> 4, c = idx & 15;
        ksT[c][j ^ c] = kg[idx];
    }
    const float4* cg = (const float4*)(g_C + (size_t)(b * LL_ + j0) * OUT_);
    C4s[tid]       = cg[tid];
    C4s[tid + 256] = cg[tid + 256];
    if (tid < 128) qs4[tid] = ((const float4*)(g_q + (size_t)(b * LL_ + i0) * HS_))[tid];
    if (tid < 32)  A4s[tid] = ((const float4*)(g_A + (size_t)(b * LL_ + i0) * OUT_))[tid];
    __syncthreads();

    // ---- Compute S[8][128]: thread -> rows {2ii2, 2ii2+1}, cols {ra, rb} ----
    {
        const int jj2 = tid & 63;
        const int ii2 = tid >> 6;
        const int ra = jj2, rb = jj2 + 64;

        ull a00[2] = {0,0}, a01[2] = {0,0}, a10[2] = {0,0}, a11[2] = {0,0};
        #pragma unroll
        for (int c = 0; c < 16; c++) {
            F4U ka, kb, qa, qb;
            ka.f = ksT[c][ra ^ c];
            kb.f = ksT[c][rb ^ c];
            qa.f = qs4[(2 * ii2 + 0) * 16 + c];
            qb.f = qs4[(2 * ii2 + 1) * 16 + c];
            fma2(a00[0], qa.u[0], ka.u[0]); fma2(a00[1], qa.u[1], ka.u[1]);
            fma2(a01[0], qa.u[0], kb.u[0]); fma2(a01[1], qa.u[1], kb.u[1]);
            fma2(a10[0], qb.u[0], ka.u[0]); fma2(a10[1], qb.u[1], ka.u[1]);
            fma2(a11[0], qb.u[0], kb.u[0]); fma2(a11[1], qb.u[1], kb.u[1]);
        }
        float2 r0, r1;
        r0 = un2(a00[0]); r1 = un2(a00[1]);
        Sd[2*ii2+0][ra] = (r0.x + r0.y) + (r1.x + r1.y);
        r0 = un2(a01[0]); r1 = un2(a01[1]);
        Sd[2*ii2+0][rb] = (r0.x + r0.y) + (r1.x + r1.y);
        r0 = un2(a10[0]); r1 = un2(a10[1]);
        Sd[2*ii2+1][ra] = (r0.x + r0.y) + (r1.x + r1.y);
        r0 = un2(a11[0]); r1 = un2(a11[1]);
        Sd[2*ii2+1][rb] = (r0.x + r0.y) + (r1.x + r1.y);
    }
    __syncthreads();

    // ---- Store phase: warp -> row ii; lanes write consecutive float4 ----
    {
        const int ii   = tid >> 5;
        const int lane = tid & 31;
        const int i    = i0 + ii;
        const int poff = i * LL_ - (i * (i - 1)) / 2;
        const float4 av = A4s[ii * 4 + (lane & 3)];
        float4* ob = (float4*)out + ((size_t)b * NPAIR + poff + (j0 - i)) * 4;

        #pragma unroll
        for (int it = 0; it < 16; it++) {
            const int idx  = lane + 32 * it;
            const int pair = idx >> 2;
            if (j0 + pair >= i) {
                const float dot = Sd[ii][pair];
                const float4 cv = C4s[idx];
                float4 r;
                r.x = dot + av.x + cv.x;
                r.y = dot + av.y + cv.y;
                r.z = dot + av.z + cv.z;
                r.w = dot + av.w + cv.w;
                ob[idx] = r;
            }
        }
    }
}

// ---------------------------------------------------------------------------
extern "C" void kernel_launch(void* const* d_in, const int* in_sizes, int n_in,
                              void* d_out, int out_size)
{
    const float* x  = (const float*)d_in[0];
    const float* Wq = (const float*)d_in[1];
    const float* bq = (const float*)d_in[2];
    const float* Wk = (const float*)d_in[3];
    const float* bk = (const float*)d_in[4];
    const float* Wb = (const float*)d_in[5];
    const float* bb = (const float*)d_in[6];
    float* out = (float*)d_out;

    proj_kernel<<<dim3(NTOK / BM_, NSPLIT), 256>>>(x, Wq, Wk);
    combine_kernel<<<NTOK / 16, 256>>>(bq, bk, Wb, bb);
    pair_kernel<<<dim3(160, BB_), 256>>>(out);
}